// round 11
// baseline (speedup 1.0000x reference)
#include <cuda_runtime.h>
#include <cuda_bf16.h>
#include <mma.h>
#include <cstdint>

using namespace nvcuda;

// Problem constants
#define B_  2
#define S_  2048
#define E_  1024
#define NH_ 16
#define NKV_ 4
#define HD_ 64
#define GS_ 4
#define MTOT (B_*S_)    // 4096

// ---------------- scratch ----------------
__device__ __align__(16) float g_q[MTOT * 1024];
__device__ __align__(16) float g_k[MTOT * 256];
__device__ __align__(16) float g_v[MTOT * 256];
__device__ __align__(16) float g_attn[MTOT * 1024];
// tf32-rounded GEMM inputs
__device__ __align__(16) float g_xq[MTOT * 1024];
__device__ __align__(16) float g_xk[MTOT * 1024];
__device__ __align__(16) float g_xv[MTOT * 1024];
__device__ __align__(16) float g_wq[1024 * 1024];
__device__ __align__(16) float g_wk[256 * 1024];
__device__ __align__(16) float g_wv[256 * 1024];
__device__ __align__(16) float g_wo[1024 * 1024];
// attention operands (pre-split bf16)
__device__ __align__(16) __nv_bfloat16 g_qah[MTOT*1024], g_qal[MTOT*1024];
__device__ __align__(16) __nv_bfloat16 g_kah[B_*NKV_*S_*HD_], g_kal[B_*NKV_*S_*HD_];
__device__ __align__(16) __nv_bfloat16 g_vth[B_*NKV_*S_*HD_], g_vtl[B_*NKV_*S_*HD_];

// ---------------- helpers ----------------
__device__ __forceinline__ uint32_t f2tf(float x) {
    uint32_t u;
    asm("cvt.rna.tf32.f32 %0, %1;" : "=r"(u) : "f"(x));
    return u;
}
__device__ __forceinline__ uint32_t pack2(float x, float y) {
    __nv_bfloat162 t = __floats2bfloat162_rn(x, y);
    return *(uint32_t*)&t;
}
__device__ __forceinline__ float bf16hi(float x) {
    return __bfloat162float(__float2bfloat16_rn(x));
}
__device__ __forceinline__ void split2(float2 v, uint32_t& hi, uint32_t& lo) {
    float hx = bf16hi(v.x), hy = bf16hi(v.y);
    hi = pack2(hx, hy);
    lo = pack2(v.x - hx, v.y - hy);
}
__device__ __forceinline__ void mma_bf16(float c[4], const uint32_t a[4],
                                         uint32_t b0, uint32_t b1)
{
    asm volatile(
        "mma.sync.aligned.m16n8k16.row.col.f32.bf16.bf16.f32 "
        "{%0,%1,%2,%3}, {%4,%5,%6,%7}, {%8,%9}, {%0,%1,%2,%3};"
        : "+f"(c[0]), "+f"(c[1]), "+f"(c[2]), "+f"(c[3])
        : "r"(a[0]), "r"(a[1]), "r"(a[2]), "r"(a[3]), "r"(b0), "r"(b1));
}
__device__ __forceinline__ void cp16(void* smem_dst, const void* gsrc) {
    uint32_t d = (uint32_t)__cvta_generic_to_shared(smem_dst);
    asm volatile("cp.async.cg.shared.global [%0], [%1], 16;" :: "r"(d), "l"(gsrc));
}
__device__ __forceinline__ void ldm4(uint32_t r[4], uint32_t addr) {
    asm volatile("ldmatrix.sync.aligned.m8n8.x4.shared.b16 {%0,%1,%2,%3}, [%4];"
        : "=r"(r[0]), "=r"(r[1]), "=r"(r[2]), "=r"(r[3]) : "r"(addr));
}

// ---------------- tf32 pre-round kernels (batched) ----------------
// activations: query/key/value, each MTOT*1024 floats (n4 = 1048576/4? -> 1M/4)
__global__ void tf32_round_act_kernel(const float4* __restrict__ a0, float4* __restrict__ o0,
                                      const float4* __restrict__ a1, float4* __restrict__ o1,
                                      const float4* __restrict__ a2, float4* __restrict__ o2,
                                      int n4)
{
    int i = blockIdx.x * blockDim.x + threadIdx.x;
    if (i >= n4) return;
    const float4* in; float4* out;
    if (blockIdx.y == 0)      { in = a0; out = o0; }
    else if (blockIdx.y == 1) { in = a1; out = o1; }
    else                      { in = a2; out = o2; }
    float4 v = in[i];
    v.x = __uint_as_float(f2tf(v.x)); v.y = __uint_as_float(f2tf(v.y));
    v.z = __uint_as_float(f2tf(v.z)); v.w = __uint_as_float(f2tf(v.w));
    out[i] = v;
}
// weights: Wq(1M), Wk(256K), Wv(256K), Wo(1M) elements
__global__ void tf32_round_w_kernel(const float4* __restrict__ a0, float4* __restrict__ o0,
                                    const float4* __restrict__ a1, float4* __restrict__ o1,
                                    const float4* __restrict__ a2, float4* __restrict__ o2,
                                    const float4* __restrict__ a3, float4* __restrict__ o3)
{
    int i = blockIdx.x * blockDim.x + threadIdx.x;
    const float4* in; float4* out; int n4;
    switch (blockIdx.y) {
        case 0: in = a0; out = o0; n4 = 1024*1024/4; break;
        case 1: in = a1; out = o1; n4 = 256*1024/4;  break;
        case 2: in = a2; out = o2; n4 = 256*1024/4;  break;
        default: in = a3; out = o3; n4 = 1024*1024/4; break;
    }
    if (i >= n4) return;
    float4 v = in[i];
    v.x = __uint_as_float(f2tf(v.x)); v.y = __uint_as_float(f2tf(v.y));
    v.z = __uint_as_float(f2tf(v.z)); v.w = __uint_as_float(f2tf(v.w));
    out[i] = v;
}

// ---------------- attention-operand conversion kernels ----------------
__global__ void conv_q_kernel(const float4* __restrict__ in,
                              uint2* __restrict__ hi, uint2* __restrict__ lo, int n4)
{
    int i = blockIdx.x * blockDim.x + threadIdx.x;
    if (i >= n4) return;
    float4 v = in[i];
    v.x *= 0.125f; v.y *= 0.125f; v.z *= 0.125f; v.w *= 0.125f;
    uint32_t h0, l0, h1, l1;
    split2(make_float2(v.x, v.y), h0, l0);
    split2(make_float2(v.z, v.w), h1, l1);
    hi[i] = make_uint2(h0, h1);
    lo[i] = make_uint2(l0, l1);
}

__global__ void conv_k_kernel(const float4* __restrict__ in,
                              uint2* __restrict__ hi, uint2* __restrict__ lo)
{
    int i = blockIdx.x * blockDim.x + threadIdx.x;
    int c4 = i & 63;
    int s  = (i >> 6) & 2047;
    int b  = i >> 17;
    int kvh = c4 >> 4, d4 = c4 & 15;
    float4 v = in[i];
    uint32_t h0, l0, h1, l1;
    split2(make_float2(v.x, v.y), h0, l0);
    split2(make_float2(v.z, v.w), h1, l1);
    int o = ((b * 4 + kvh) * 2048 + s) * 16 + d4;
    hi[o] = make_uint2(h0, h1);
    lo[o] = make_uint2(l0, l1);
}

__global__ void conv_vt_kernel(const float* __restrict__ V,
                               __nv_bfloat16* __restrict__ vth,
                               __nv_bfloat16* __restrict__ vtl)
{
    __shared__ float ts[32][33];
    const int s0 = blockIdx.x * 32, d0 = blockIdx.y * 32;
    const int bh = blockIdx.z;
    const int b = bh >> 2, kvh = bh & 3;
    const int x = threadIdx.x, y = threadIdx.y;

    #pragma unroll
    for (int l = 0; l < 4; l++) {
        int s = s0 + y + l * 8;
        ts[y + l * 8][x] = V[((size_t)(b * 2048 + s)) * 256 + kvh * 64 + d0 + x];
    }
    __syncthreads();
    #pragma unroll
    for (int l = 0; l < 4; l++) {
        int d = d0 + y + l * 8;
        float f = ts[x][y + l * 8];
        float h = bf16hi(f);
        size_t o = ((size_t)(bh * 64 + d)) * 2048 + s0 + x;
        vth[o] = __float2bfloat16_rn(h);
        vtl[o] = __float2bfloat16_rn(f - h);
    }
}

// ---------------------------------------------------------------------------
// tf32 GEMM, 3-stage cp.async, inputs pre-rounded to tf32 (no cvt in loop).
// ---------------------------------------------------------------------------
#define GBK 16
#define GPAD 20
#define GSTAGE_F (128 * GPAD)

__device__ __forceinline__ void gemm_body(const float* __restrict__ X,
                                          const float* __restrict__ W,
                                          float* __restrict__ C,
                                          int M, int N, int K, float* sm)
{
    float* Xs = sm;
    float* Ws = sm + 3 * GSTAGE_F;

    const int tid = threadIdx.x;
    const int wid = tid >> 5;
    const int wr  = wid & 1;
    const int wc  = wid >> 1;
    const int m0  = blockIdx.y * 128;
    const int n0  = blockIdx.x * 128;

    wmma::fragment<wmma::accumulator, 16, 16, 8, float> acc[4][2];
    #pragma unroll
    for (int i = 0; i < 4; i++)
        #pragma unroll
        for (int j = 0; j < 2; j++)
            wmma::fill_fragment(acc[i][j], 0.0f);

    auto prefetch = [&](int kt, int st) {
        const int k0 = kt * GBK;
        float* xs = Xs + st * GSTAGE_F;
        float* ws = Ws + st * GSTAGE_F;
        #pragma unroll
        for (int l = 0; l < 2; l++) {
            int idx = tid + l * 256;
            int r   = idx >> 2;
            int c4  = idx & 3;
            cp16(&xs[r * GPAD + c4 * 4], &X[(size_t)(m0 + r) * K + k0 + c4 * 4]);
            cp16(&ws[r * GPAD + c4 * 4], &W[(size_t)(n0 + r) * K + k0 + c4 * 4]);
        }
        asm volatile("cp.async.commit_group;");
    };

    const int nKT = K / GBK;
    prefetch(0, 0);
    if (nKT > 1) prefetch(1, 1);

    int pst = 2;
    for (int kt = 0; kt < nKT; kt++) {
        asm volatile("cp.async.wait_group 1;");
        __syncthreads();
        if (kt + 2 < nKT) {
            prefetch(kt + 2, pst);
            pst = (pst + 1 == 3) ? 0 : pst + 1;
        } else {
            asm volatile("cp.async.commit_group;");
        }
        const int st = kt % 3;
        const float* xs = Xs + st * GSTAGE_F;
        const float* ws = Ws + st * GSTAGE_F;

        #pragma unroll
        for (int ks = 0; ks < GBK; ks += 8) {
            wmma::fragment<wmma::matrix_a, 16, 16, 8, wmma::precision::tf32, wmma::row_major> a[4];
            wmma::fragment<wmma::matrix_b, 16, 16, 8, wmma::precision::tf32, wmma::col_major> bfr[2];
            #pragma unroll
            for (int i = 0; i < 4; i++)
                wmma::load_matrix_sync(a[i], &xs[(wr * 64 + i * 16) * GPAD + ks], GPAD);
            #pragma unroll
            for (int j = 0; j < 2; j++)
                wmma::load_matrix_sync(bfr[j], &ws[(wc * 32 + j * 16) * GPAD + ks], GPAD);
            #pragma unroll
            for (int i = 0; i < 4; i++)
                #pragma unroll
                for (int j = 0; j < 2; j++)
                    wmma::mma_sync(acc[i][j], a[i], bfr[j], acc[i][j]);
        }
    }

    #pragma unroll
    for (int i = 0; i < 4; i++)
        #pragma unroll
        for (int j = 0; j < 2; j++)
            wmma::store_matrix_sync(&C[(size_t)(m0 + wr * 64 + i * 16) * N + n0 + wc * 32 + j * 16],
                                    acc[i][j], N, wmma::mem_row_major);
}

__global__ __launch_bounds__(256, 2)
void gemm_q_kernel(const float* __restrict__ X, const float* __restrict__ W,
                   float* __restrict__ C, int M, int N, int K)
{
    extern __shared__ float sm[];
    gemm_body(X, W, C, M, N, K, sm);
}

__global__ __launch_bounds__(256, 2)
void gemm_kv_kernel(const float* __restrict__ X0, const float* __restrict__ W0, float* __restrict__ C0,
                    const float* __restrict__ X1, const float* __restrict__ W1, float* __restrict__ C1,
                    int M, int N, int K)
{
    extern __shared__ float sm[];
    if (blockIdx.z == 0) gemm_body(X0, W0, C0, M, N, K, sm);
    else                 gemm_body(X1, W1, C1, M, N, K, sm);
}

// ---------------------------------------------------------------------------
// Flash attention: BQ=128 (8 warps), BK=32, bf16 hi/lo mma, ldmatrix feeds,
// 2-stage cp.async double buffering. Writes tf32-rounded f32 output.
// ---------------------------------------------------------------------------
#define ABQ 128
#define ABK 32

__global__ __launch_bounds__(256, 2)
void attn_mma_kernel(const uint32_t* __restrict__ qh, const uint32_t* __restrict__ ql,
                     const __nv_bfloat16* __restrict__ kh, const __nv_bfloat16* __restrict__ kl,
                     const __nv_bfloat16* __restrict__ vth, const __nv_bfloat16* __restrict__ vtl,
                     float* __restrict__ O)
{
    __shared__ __align__(16) uint32_t sK[2][2][32 * 36];   // [stage][hi/lo]
    __shared__ __align__(16) uint32_t sV[2][2][64 * 20];

    const int qb   = gridDim.x - 1 - blockIdx.x;
    const int h    = blockIdx.y;
    const int b    = blockIdx.z;
    const int kvh  = h >> 2;
    const int tid  = threadIdx.x;
    const int lane = tid & 31;
    const int w    = tid >> 5;          // 0..7
    const int g    = lane >> 2;
    const int tig  = lane & 3;

    const int r0g = qb * ABQ + w * 16 + g;
    const int r1g = r0g + 8;

    const int sel  = lane >> 3;
    const int rowm = lane & 7;
    const int kofsB = ((((sel >> 1) * 8 + rowm) * 36) + (sel & 1) * 4) * 4;
    const int vofsB = ((((sel >> 1) * 8 + rowm) * 20) + (sel & 1) * 4) * 4;

    // ---- Q A-fragments (one-time) ----
    uint32_t qhi[4][4], qlo[4][4];
    {
        const size_t b0 = (((size_t)(b * S_ + r0g)) * 1024 + h * 64) >> 1;
        const size_t b1 = (((size_t)(b * S_ + r1g)) * 1024 + h * 64) >> 1;
        #pragma unroll
        for (int kc = 0; kc < 4; kc++) {
            int c0 = kc * 8 + tig, c1 = c0 + 4;
            qhi[kc][0] = qh[b0 + c0]; qhi[kc][1] = qh[b1 + c0];
            qhi[kc][2] = qh[b0 + c1]; qhi[kc][3] = qh[b1 + c1];
            qlo[kc][0] = ql[b0 + c0]; qlo[kc][1] = ql[b1 + c0];
            qlo[kc][2] = ql[b0 + c1]; qlo[kc][3] = ql[b1 + c1];
        }
    }

    float oacc[8][4];
    #pragma unroll
    for (int nb = 0; nb < 8; nb++)
        #pragma unroll
        for (int e = 0; e < 4; e++) oacc[nb][e] = 0.f;
    float m0 = -1e30f, m1 = -1e30f, l0 = 0.f, l1 = 0.f;

    const int wRowMax = qb * ABQ + w * 16 + 15;
    const int nKT = 4 * qb + 4;
    const size_t kbase = ((size_t)(b * NKV_ + kvh)) * S_ * 64;
    const size_t vbase = ((size_t)(b * NKV_ + kvh)) * 64 * S_;

    auto load_tile = [&](int kt, int st) {
        #pragma unroll
        for (int l = 0; l < 4; l++) {
            int idx = tid + l * 256;                  // 0..1023
            if (idx < 512) {
                int c = idx & 7, r = (idx >> 3) & 31, hl = idx >> 8;
                const __nv_bfloat16* src = (hl ? kl : kh) + kbase + (size_t)(kt * 32 + r) * 64 + c * 8;
                cp16(&sK[st][hl][r * 36 + c * 4], src);
            } else {
                int j = idx - 512;
                int c = j & 3, d = (j >> 2) & 63, hl = j >> 8;
                const __nv_bfloat16* src = (hl ? vtl : vth) + vbase + (size_t)d * S_ + kt * 32 + c * 8;
                cp16(&sV[st][hl][d * 20 + c * 4], src);
            }
        }
        asm volatile("cp.async.commit_group;");
    };

    load_tile(0, 0);

    for (int kt = 0; kt < nKT; kt++) {
        asm volatile("cp.async.wait_group 0;");
        __syncthreads();
        if (kt + 1 < nKT) load_tile(kt + 1, (kt + 1) & 1);
        const int st = kt & 1;

        if (kt * ABK <= wRowMax) {
            const uint32_t aKhi = (uint32_t)__cvta_generic_to_shared(&sK[st][0][0]);
            const uint32_t aKlo = (uint32_t)__cvta_generic_to_shared(&sK[st][1][0]);
            const uint32_t aVhi = (uint32_t)__cvta_generic_to_shared(&sV[st][0][0]);
            const uint32_t aVlo = (uint32_t)__cvta_generic_to_shared(&sV[st][1][0]);

            // ---- S = Q @ K^T ----
            float sacc[4][4];
            #pragma unroll
            for (int nb = 0; nb < 4; nb++)
                #pragma unroll
                for (int e = 0; e < 4; e++) sacc[nb][e] = 0.f;

            #pragma unroll
            for (int kc = 0; kc < 4; kc++) {
                #pragma unroll
                for (int nbp = 0; nbp < 2; nbp++) {
                    uint32_t off = (uint32_t)((nbp * 16 * 36 + kc * 8) * 4) + kofsB;
                    uint32_t H[4], L[4];
                    ldm4(H, aKhi + off);
                    ldm4(L, aKlo + off);
                    mma_bf16(sacc[2*nbp],   qhi[kc], L[0], L[1]);
                    mma_bf16(sacc[2*nbp],   qlo[kc], H[0], H[1]);
                    mma_bf16(sacc[2*nbp],   qhi[kc], H[0], H[1]);
                    mma_bf16(sacc[2*nbp+1], qhi[kc], L[2], L[3]);
                    mma_bf16(sacc[2*nbp+1], qlo[kc], H[2], H[3]);
                    mma_bf16(sacc[2*nbp+1], qhi[kc], H[2], H[3]);
                }
            }

            // ---- causal mask + online softmax ----
            float mn0 = m0, mn1 = m1;
            #pragma unroll
            for (int nb = 0; nb < 4; nb++) {
                #pragma unroll
                for (int e = 0; e < 2; e++) {
                    int col = kt * ABK + nb * 8 + 2 * tig + e;
                    if (col > r0g) sacc[nb][e]     = -1e30f;
                    if (col > r1g) sacc[nb][e + 2] = -1e30f;
                    mn0 = fmaxf(mn0, sacc[nb][e]);
                    mn1 = fmaxf(mn1, sacc[nb][e + 2]);
                }
            }
            mn0 = fmaxf(mn0, __shfl_xor_sync(0xffffffffu, mn0, 1));
            mn0 = fmaxf(mn0, __shfl_xor_sync(0xffffffffu, mn0, 2));
            mn1 = fmaxf(mn1, __shfl_xor_sync(0xffffffffu, mn1, 1));
            mn1 = fmaxf(mn1, __shfl_xor_sync(0xffffffffu, mn1, 2));

            const float corr0 = __expf(m0 - mn0);
            const float corr1 = __expf(m1 - mn1);
            m0 = mn0; m1 = mn1;
            l0 *= corr0; l1 *= corr1;
            #pragma unroll
            for (int nb = 0; nb < 8; nb++) {
                oacc[nb][0] *= corr0; oacc[nb][1] *= corr0;
                oacc[nb][2] *= corr1; oacc[nb][3] *= corr1;
            }

            #pragma unroll
            for (int nb = 0; nb < 4; nb++) {
                sacc[nb][0] = __expf(sacc[nb][0] - mn0);
                sacc[nb][1] = __expf(sacc[nb][1] - mn0);
                sacc[nb][2] = __expf(sacc[nb][2] - mn1);
                sacc[nb][3] = __expf(sacc[nb][3] - mn1);
                l0 += sacc[nb][0] + sacc[nb][1];
                l1 += sacc[nb][2] + sacc[nb][3];
            }

            // ---- O += P @ V ----
            #pragma unroll
            for (int kc2 = 0; kc2 < 2; kc2++) {
                uint32_t phi[4], plo[4];
                split2(make_float2(sacc[2*kc2][0],     sacc[2*kc2][1]),     phi[0], plo[0]);
                split2(make_float2(sacc[2*kc2][2],     sacc[2*kc2][3]),     phi[1], plo[1]);
                split2(make_float2(sacc[2*kc2 + 1][0], sacc[2*kc2 + 1][1]), phi[2], plo[2]);
                split2(make_float2(sacc[2*kc2 + 1][2], sacc[2*kc2 + 1][3]), phi[3], plo[3]);
                #pragma unroll
                for (int nbp = 0; nbp < 4; nbp++) {
                    uint32_t off = (uint32_t)((nbp * 16 * 20 + kc2 * 8) * 4) + vofsB;
                    uint32_t H[4], L[4];
                    ldm4(H, aVhi + off);
                    ldm4(L, aVlo + off);
                    mma_bf16(oacc[2*nbp],   phi, L[0], L[1]);
                    mma_bf16(oacc[2*nbp],   plo, H[0], H[1]);
                    mma_bf16(oacc[2*nbp],   phi, H[0], H[1]);
                    mma_bf16(oacc[2*nbp+1], phi, L[2], L[3]);
                    mma_bf16(oacc[2*nbp+1], plo, H[2], H[3]);
                    mma_bf16(oacc[2*nbp+1], phi, H[2], H[3]);
                }
            }
        }
        __syncthreads();
    }

    // ---- epilogue: normalize + tf32-round (O-proj input) ----
    l0 += __shfl_xor_sync(0xffffffffu, l0, 1);
    l0 += __shfl_xor_sync(0xffffffffu, l0, 2);
    l1 += __shfl_xor_sync(0xffffffffu, l1, 1);
    l1 += __shfl_xor_sync(0xffffffffu, l1, 2);
    const float inv0 = 1.f / l0;
    const float inv1 = 1.f / l1;

    float* op0 = O + ((size_t)(b * S_ + r0g)) * 1024 + h * 64;
    float* op1 = O + ((size_t)(b * S_ + r1g)) * 1024 + h * 64;
    #pragma unroll
    for (int nb = 0; nb < 8; nb++) {
        *(float2*)&op0[nb * 8 + 2 * tig] = make_float2(
            __uint_as_float(f2tf(oacc[nb][0] * inv0)),
            __uint_as_float(f2tf(oacc[nb][1] * inv0)));
        *(float2*)&op1[nb * 8 + 2 * tig] = make_float2(
            __uint_as_float(f2tf(oacc[nb][2] * inv1)),
            __uint_as_float(f2tf(oacc[nb][3] * inv1)));
    }
}

// ---------------------------------------------------------------------------
// Launch. Inputs: 0 query, 1 key, 2 value, 3 attn_mask, 4 Wq, 5 Wk, 6 Wv, 7 Wo
// ---------------------------------------------------------------------------
extern "C" void kernel_launch(void* const* d_in, const int* in_sizes, int n_in,
                              void* d_out, int out_size)
{
    const float* query = (const float*)d_in[0];
    const float* key   = (const float*)d_in[1];
    const float* value = (const float*)d_in[2];
    const float* Wq    = (const float*)d_in[4];
    const float* Wk    = (const float*)d_in[5];
    const float* Wv    = (const float*)d_in[6];
    const float* Wo    = (const float*)d_in[7];
    float* out = (float*)d_out;

    float *q, *k, *v, *attn;
    float *xq, *xk, *xv, *wq, *wk, *wv, *wo;
    cudaGetSymbolAddress((void**)&q,    g_q);
    cudaGetSymbolAddress((void**)&k,    g_k);
    cudaGetSymbolAddress((void**)&v,    g_v);
    cudaGetSymbolAddress((void**)&attn, g_attn);
    cudaGetSymbolAddress((void**)&xq, g_xq);
    cudaGetSymbolAddress((void**)&xk, g_xk);
    cudaGetSymbolAddress((void**)&xv, g_xv);
    cudaGetSymbolAddress((void**)&wq, g_wq);
    cudaGetSymbolAddress((void**)&wk, g_wk);
    cudaGetSymbolAddress((void**)&wv, g_wv);
    cudaGetSymbolAddress((void**)&wo, g_wo);
    __nv_bfloat16 *qah, *qal, *kah, *kal, *vth, *vtl;
    cudaGetSymbolAddress((void**)&qah, g_qah); cudaGetSymbolAddress((void**)&qal, g_qal);
    cudaGetSymbolAddress((void**)&kah, g_kah); cudaGetSymbolAddress((void**)&kal, g_kal);
    cudaGetSymbolAddress((void**)&vth, g_vth); cudaGetSymbolAddress((void**)&vtl, g_vtl);

    const int dynsmem = 6 * GSTAGE_F * 4;   // 61440 B
    cudaFuncSetAttribute(gemm_q_kernel,  cudaFuncAttributeMaxDynamicSharedMemorySize, dynsmem);
    cudaFuncSetAttribute(gemm_kv_kernel, cudaFuncAttributeMaxDynamicSharedMemorySize, dynsmem);

    // ---- pre-round GEMM inputs to tf32 ----
    tf32_round_act_kernel<<<dim3(4096, 3), 256>>>(
        (const float4*)query, (float4*)xq,
        (const float4*)key,   (float4*)xk,
        (const float4*)value, (float4*)xv, MTOT*1024/4);
    tf32_round_w_kernel<<<dim3(1024, 4), 256>>>(
        (const float4*)Wq, (float4*)wq, (const float4*)Wk, (float4*)wk,
        (const float4*)Wv, (float4*)wv, (const float4*)Wo, (float4*)wo);

    // ---- projections (tf32) ----
    gemm_q_kernel<<<dim3(8, 32), 256, dynsmem>>>(xq, wq, q, MTOT, 1024, 1024);
    gemm_kv_kernel<<<dim3(2, 32, 2), 256, dynsmem>>>(xk, wk, k, xv, wv, v, MTOT, 256, 1024);

    // ---- convert attention operands ----
    conv_q_kernel<<<4096, 256>>>((const float4*)q, (uint2*)qah, (uint2*)qal, MTOT*1024/4);
    conv_k_kernel<<<1024, 256>>>((const float4*)k, (uint2*)kah, (uint2*)kal);
    conv_vt_kernel<<<dim3(S_/32, HD_/32, B_*NKV_), dim3(32, 8)>>>(v, vth, vtl);

    // ---- attention ----
    attn_mma_kernel<<<dim3(S_/ABQ, NH_, B_), 256>>>(
        (const uint32_t*)qah, (const uint32_t*)qal, kah, kal, vth, vtl, attn);

    // ---- output projection (tf32) ----
    gemm_q_kernel<<<dim3(8, 32), 256, dynsmem>>>(attn, wo, out, MTOT, 1024, 1024);
}